// round 5
// baseline (speedup 1.0000x reference)
#include <cuda_runtime.h>
#include <cstdint>

#define B     16
#define S     1024
#define D     512
#define KC    12
#define K     10
#define NDS   16          // d-slices per batch
#define DSW   32          // d per slice
#define NT    256
#define TILES 4
#define TS    256         // s per tile
#define NSG   32          // s-groups (sg = tid>>3, dp = tid&7)
#define SITER (TS / NSG)  // 8 s per thread per tile
#define NITER (TILES * SITER)  // 32
#define STG   6           // ring slots
#define PFD   5           // prefetch distance

typedef unsigned long long ull;
#define ONE2 0x3f8000003f800000ull

__device__ float g_sqpart[B][K][NDS];
__device__ int   g_cnt[B];

__device__ __forceinline__ void fma2(ull& acc, ull a, ull f) {
    asm("fma.rn.f32x2 %0, %1, %2, %0;" : "+l"(acc) : "l"(a), "l"(f));
}
__device__ __forceinline__ uint32_t s2u(const void* p) {
    uint32_t a;
    asm("{ .reg .u64 t; cvta.to.shared.u64 t, %1; cvt.u32.u64 %0, t; }" : "=r"(a) : "l"(p));
    return a;
}
__device__ __forceinline__ void cpa16(uint32_t dst, ull gsrc) {
    asm volatile("cp.async.cg.shared.global [%0], [%1], 16;" :: "r"(dst), "l"(gsrc) : "memory");
}
#define CP_COMMIT() asm volatile("cp.async.commit_group;" ::: "memory")
#define CP_WAIT()   asm volatile("cp.async.wait_group 4;" ::: "memory")

__global__ __launch_bounds__(NT, 2)
void vlad_fused(const float* __restrict__ feat, const float* __restrict__ score,
                const float* __restrict__ cluster, float* __restrict__ out)
{
    __shared__ __align__(16) ull Ash[TS][K];        // 20 KB (reused as reduce buf)
    __shared__ __align__(16) float4 ring[STG][NT];  // 24 KB self-staging ring
    __shared__ float wsum[8][K];
    __shared__ float asumS[K];
    __shared__ float invS[K];
    __shared__ int   isLast;

    const int tid = threadIdx.x;
    const int b  = blockIdx.x >> 4;
    const int ds = blockIdx.x & 15;
    const int d0 = ds * DSW;
    const int dp = tid & 7;
    const int sg = tid >> 3;

    // global-space byte address of this thread's feat element at stage 0;
    // stage gi is at +gi*65536 bytes  (s = 32*gi + sg)
    ull g0;
    {
        const float* p = feat + ((size_t)b * S + sg) * D + d0 + dp * 4;
        asm("cvta.to.global.u64 %0, %1;" : "=l"(g0) : "l"(p));
    }
    const uint32_t rb = s2u(&ring[0][0]) + tid * 16;   // + slot*4096

    // ---- prologue: prime PFD stages (one commit group per stage) ----
    #pragma unroll
    for (int p = 0; p < PFD; p++) {
        cpa16(rb + p * 4096, g0 + (ull)p * 65536ull);
        CP_COMMIT();
    }

    ull acc[K][2];
    #pragma unroll
    for (int k = 0; k < K; k++) { acc[k][0] = 0ull; acc[k][1] = 0ull; }
    float asumr[K];
    #pragma unroll
    for (int k = 0; k < K; k++) asumr[k] = 0.f;

    int rd = 0, wr = PFD;   // ring slot cursors (mod STG)

    for (int T = 0; T < TILES; T++) {
        // ---- softmax for s = T*256 + tid (one row per thread) ----
        {
            const float* sp = score + ((size_t)(b * S) + T * TS + tid) * KC;
            float4 v0 = *(const float4*)sp;
            float4 v1 = *(const float4*)(sp + 4);
            float4 v2 = *(const float4*)(sp + 8);
            float v[KC] = {v0.x, v0.y, v0.z, v0.w, v1.x, v1.y, v1.z, v1.w,
                           v2.x, v2.y, v2.z, v2.w};
            float sum = 0.f;
            #pragma unroll
            for (int k = 0; k < KC; k++) { v[k] = __expf(v[k]); sum += v[k]; }
            float inv = 1.f / sum;
            #pragma unroll
            for (int k = 0; k < K; k++) {
                float a = v[k] * inv;
                asumr[k] += a;
                unsigned int u = __float_as_uint(a);
                Ash[tid][k] = ((ull)u << 32) | (ull)u;
            }
        }
        __syncthreads();

        // ---- main loop: stage gi = T*8+il holds s = sg + 32*il (this tile) ----
        #pragma unroll
        for (int il = 0; il < SITER; il++) {
            const int gi = T * SITER + il;
            CP_WAIT();                                  // stage gi landed
            ulonglong2 f = *(const ulonglong2*)&ring[rd][tid];
            rd = (rd == STG - 1) ? 0 : rd + 1;

            const ulonglong2* ar = (const ulonglong2*)Ash[sg + il * NSG];
            ulonglong2 a01 = ar[0], a23 = ar[1], a45 = ar[2], a67 = ar[3], a89 = ar[4];
            fma2(acc[0][0], a01.x, f.x); fma2(acc[0][1], a01.x, f.y);
            fma2(acc[1][0], a01.y, f.x); fma2(acc[1][1], a01.y, f.y);
            fma2(acc[2][0], a23.x, f.x); fma2(acc[2][1], a23.x, f.y);
            fma2(acc[3][0], a23.y, f.x); fma2(acc[3][1], a23.y, f.y);
            fma2(acc[4][0], a45.x, f.x); fma2(acc[4][1], a45.x, f.y);
            fma2(acc[5][0], a45.y, f.x); fma2(acc[5][1], a45.y, f.y);
            fma2(acc[6][0], a67.x, f.x); fma2(acc[6][1], a67.x, f.y);
            fma2(acc[7][0], a67.y, f.x); fma2(acc[7][1], a67.y, f.y);
            fma2(acc[8][0], a89.x, f.x); fma2(acc[8][1], a89.x, f.y);
            fma2(acc[9][0], a89.y, f.x); fma2(acc[9][1], a89.y, f.y);

            const int pi = gi + PFD;
            if (pi < NITER) cpa16(rb + wr * 4096, g0 + (ull)pi * 65536ull);
            wr = (wr == STG - 1) ? 0 : wr + 1;
            CP_COMMIT();                                // one group per iter (may be empty)
        }
        __syncthreads();   // protect Ash before next tile / reduction reuse
    }

    // ---- block-reduce asum ----
    #pragma unroll
    for (int k = 0; k < K; k++) {
        float v = asumr[k];
        #pragma unroll
        for (int o = 16; o > 0; o >>= 1) v += __shfl_xor_sync(0xffffffffu, v, o);
        if ((tid & 31) == 0) wsum[tid >> 5][k] = v;
    }
    __syncthreads();
    if (tid < K) {
        float s = 0.f;
        #pragma unroll
        for (int w = 0; w < 8; w++) s += wsum[w][tid];
        asumS[tid] = s;
    }

    // ---- reduce acc over the 32 s-groups (tree in smem, reusing Ash) ----
    ull* buf = &Ash[0][0];            // 2560 ull = 20 KB, exactly enough
    ull* accp = &acc[0][0];
    #pragma unroll
    for (int h = 16; h > 0; h >>= 1) {
        __syncthreads();
        if (sg >= h && sg < 2 * h) {
            ull* row = buf + ((sg - h) * 8 + dp) * 20;
            #pragma unroll
            for (int j = 0; j < 20; j++) row[j] = accp[j];
        }
        __syncthreads();
        if (sg < h) {
            const ull* row = buf + (sg * 8 + dp) * 20;
            #pragma unroll
            for (int j = 0; j < 20; j++) fma2(accp[j], row[j], ONE2);
        }
    }

    // ---- epilogue: 8 threads (sg==0) hold totals for 10k x 4d ----
    if (sg == 0) {
        #pragma unroll
        for (int k = 0; k < K; k++) {
            float as = asumS[k];
            float4 cl = *(const float4*)(cluster + k * D + d0 + dp * 4);
            float rx = __uint_as_float((unsigned int)acc[k][0])         - as * cl.x;
            float ry = __uint_as_float((unsigned int)(acc[k][0] >> 32)) - as * cl.y;
            float rz = __uint_as_float((unsigned int)acc[k][1])         - as * cl.z;
            float rw = __uint_as_float((unsigned int)(acc[k][1] >> 32)) - as * cl.w;
            *(float4*)(out + ((size_t)(b * K) + k) * D + d0 + dp * 4) =
                make_float4(rx, ry, rz, rw);
            float sq = rx * rx + ry * ry + rz * rz + rw * rw;
            sq += __shfl_xor_sync(0x000000ffu, sq, 4);
            sq += __shfl_xor_sync(0x000000ffu, sq, 2);
            sq += __shfl_xor_sync(0x000000ffu, sq, 1);
            if (dp == 0) g_sqpart[b][k][ds] = sq;
        }
    }

    // ---- last CTA of this batch performs the L2 normalization ----
    __threadfence();
    __syncthreads();
    if (tid == 0) {
        int old = atomicAdd(&g_cnt[b], 1);
        isLast = (old == NDS - 1);
    }
    __syncthreads();
    if (isLast) {
        __threadfence();
        if (tid < K) {
            float s = 0.f;
            #pragma unroll
            for (int p = 0; p < NDS; p++) s += g_sqpart[b][tid][p];
            invS[tid] = rsqrtf(fmaxf(s, 1e-12f));
        }
        __syncthreads();
        float4* o4 = (float4*)out + (size_t)b * (K * D / 4);   // 1280 float4
        #pragma unroll
        for (int j = 0; j < 5; j++) {
            int idx = tid + j * NT;
            float iv = invS[idx >> 7];
            float4 v = o4[idx];
            v.x *= iv; v.y *= iv; v.z *= iv; v.w *= iv;
            o4[idx] = v;
        }
        if (tid == 0) g_cnt[b] = 0;   // reset for next graph replay
    }
}

extern "C" void kernel_launch(void* const* d_in, const int* in_sizes, int n_in,
                              void* d_out, int out_size) {
    const float* feat    = (const float*)d_in[0];  // (16,16,64,512) f32
    const float* score   = (const float*)d_in[1];  // (16,16,64,12)  f32
    const float* cluster = (const float*)d_in[2];  // (12,512)       f32
    float* out = (float*)d_out;                    // (16,5120)      f32

    vlad_fused<<<B * NDS, NT>>>(feat, score, cluster, out);
}

// round 6
// speedup vs baseline: 1.0017x; 1.0017x over previous
#include <cuda_runtime.h>
#include <cstdint>

#define Bn    16
#define Sn    1024
#define Dn    512
#define KCn   12
#define Kn    10
#define NSC   16          // s-chunks per batch (64 s each)
#define CSL   64
#define NT    256
#define NSTG  8           // stages per chunk (8 s-rows = 16 KB each)
#define RSZ   16384
#define NSLOT 3
#define DYN_BYTES (NSLOT * RSZ + CSL * Kn * 8)   // ring 48 KB + Ash 5 KB

typedef unsigned long long ull;
#define ONE2 0x3f8000003f800000ull

__device__ float g_part[Bn * NSC][Kn][Dn];   // 5.24 MB partials
__device__ float g_asum[Bn * NSC][Kn];
__device__ int   g_cnt[Bn];

__device__ __forceinline__ void fma2(ull& acc, ull a, ull f) {
    asm("fma.rn.f32x2 %0, %1, %2, %0;" : "+l"(acc) : "l"(a), "l"(f));
}
__device__ __forceinline__ uint32_t s2u(const void* p) {
    uint32_t a;
    asm("{ .reg .u64 t; cvta.to.shared.u64 t, %1; cvt.u32.u64 %0, t; }" : "=r"(a) : "l"(p));
    return a;
}
__device__ __forceinline__ void mbar_init(uint32_t mb, uint32_t cnt) {
    asm volatile("mbarrier.init.shared.b64 [%0], %1;" :: "r"(mb), "r"(cnt) : "memory");
}
__device__ __forceinline__ void mbar_expect_tx(uint32_t mb, uint32_t bytes) {
    asm volatile("mbarrier.arrive.expect_tx.shared.b64 _, [%0], %1;"
                 :: "r"(mb), "r"(bytes) : "memory");
}
__device__ __forceinline__ void bulk_g2s(uint32_t dst, ull gsrc, uint32_t bytes, uint32_t mb) {
    asm volatile("cp.async.bulk.shared::cluster.global.mbarrier::complete_tx::bytes "
                 "[%0], [%1], %2, [%3];"
                 :: "r"(dst), "l"(gsrc), "r"(bytes), "r"(mb) : "memory");
}
__device__ __forceinline__ void mbar_wait(uint32_t mb, uint32_t parity) {
    uint32_t done;
    asm volatile("{\n\t.reg .pred p;\n\t"
                 "mbarrier.try_wait.parity.acquire.cta.shared::cta.b64 p, [%1], %2;\n\t"
                 "selp.b32 %0, 1, 0, p;\n\t}"
                 : "=r"(done) : "r"(mb), "r"(parity) : "memory");
    if (!done) {
        asm volatile("{\n\t.reg .pred P1;\n\t"
                     "W%=:\n\t"
                     "mbarrier.try_wait.parity.acquire.cta.shared::cta.b64 P1, [%0], %1, 0x989680;\n\t"
                     "@P1 bra.uni DW%=;\n\t"
                     "bra.uni W%=;\n\t"
                     "DW%=:\n\t}"
                     :: "r"(mb), "r"(parity) : "memory");
    }
}

__global__ __launch_bounds__(NT, 2)
void vlad_bulk(const float* __restrict__ feat, const float* __restrict__ score,
               const float* __restrict__ cluster, float* __restrict__ out)
{
    extern __shared__ __align__(16) char dyn[];
    ull (*Ash)[Kn] = (ull(*)[Kn])(dyn + NSLOT * RSZ);
    __shared__ __align__(8) ull mbar[NSLOT];
    __shared__ float wsum[2][Kn];
    __shared__ float asumT[Kn];
    __shared__ float invS[Kn];
    __shared__ int   isLast;

    const int tid = threadIdx.x;
    const int b  = blockIdx.x >> 4;
    const int sc = blockIdx.x & 15;
    const int sp = tid >> 7;          // s parity within stage
    const int dg = tid & 127;         // d-group (4 floats)

    const uint32_t ringA = s2u(dyn);
    const uint32_t mbA   = s2u(&mbar[0]);

    // global byte address of this CTA's contiguous 128 KB feat span
    ull g0;
    {
        const float* p = feat + ((size_t)b * Sn + sc * CSL) * Dn;
        asm("cvta.to.global.u64 %0, %1;" : "=l"(g0) : "l"(p));
    }

    if (tid == 0) {
        #pragma unroll
        for (int s = 0; s < NSLOT; s++) mbar_init(mbA + s * 8, 1);
    }
    __syncthreads();
    if (tid == 0) {   // prime 2 stages while softmax runs
        #pragma unroll
        for (int p = 0; p < 2; p++) {
            mbar_expect_tx(mbA + p * 8, RSZ);
            bulk_g2s(ringA + p * RSZ, g0 + (ull)p * RSZ, RSZ, mbA + p * 8);
        }
    }

    // ---- softmax for my chunk's 64 rows (tid < 64, one full row each) ----
    if (tid < CSL) {
        const float* sprow = score + ((size_t)(b * Sn) + sc * CSL + tid) * KCn;
        float4 v0 = *(const float4*)sprow;
        float4 v1 = *(const float4*)(sprow + 4);
        float4 v2 = *(const float4*)(sprow + 8);
        float v[KCn] = {v0.x, v0.y, v0.z, v0.w, v1.x, v1.y, v1.z, v1.w,
                        v2.x, v2.y, v2.z, v2.w};
        float sum = 0.f;
        #pragma unroll
        for (int k = 0; k < KCn; k++) { v[k] = __expf(v[k]); sum += v[k]; }
        float inv = 1.f / sum;
        float a[Kn];
        #pragma unroll
        for (int k = 0; k < Kn; k++) {
            a[k] = v[k] * inv;
            unsigned int u = __float_as_uint(a[k]);
            Ash[tid][k] = ((ull)u << 32) | (ull)u;
        }
        #pragma unroll
        for (int k = 0; k < Kn; k++) {
            float s = a[k];
            #pragma unroll
            for (int o = 16; o > 0; o >>= 1) s += __shfl_xor_sync(0xffffffffu, s, o);
            if ((tid & 31) == 0) wsum[tid >> 5][k] = s;
        }
    }
    __syncthreads();
    if (tid < Kn) g_asum[b * NSC + sc][tid] = wsum[0][tid] + wsum[1][tid];

    // ---- main loop over 8 stages; thread owns 4 d, rows sp, sp+2, sp+4, sp+6 ----
    ull acc[Kn][2];
    #pragma unroll
    for (int k = 0; k < Kn; k++) { acc[k][0] = 0ull; acc[k][1] = 0ull; }

    for (int st = 0; st < NSTG; st++) {
        const int slot = st % NSLOT;
        mbar_wait(mbA + slot * 8, (uint32_t)((st / NSLOT) & 1));

        const ull* rs = (const ull*)(dyn + slot * RSZ);
        #pragma unroll
        for (int r4 = 0; r4 < 4; r4++) {
            const int row = r4 * 2 + sp;
            ulonglong2 f = *(const ulonglong2*)(rs + (size_t)row * 256 + dg * 2);
            const ulonglong2* ar = (const ulonglong2*)Ash[st * 8 + row];
            ulonglong2 a01 = ar[0], a23 = ar[1], a45 = ar[2], a67 = ar[3], a89 = ar[4];
            fma2(acc[0][0], a01.x, f.x); fma2(acc[0][1], a01.x, f.y);
            fma2(acc[1][0], a01.y, f.x); fma2(acc[1][1], a01.y, f.y);
            fma2(acc[2][0], a23.x, f.x); fma2(acc[2][1], a23.x, f.y);
            fma2(acc[3][0], a23.y, f.x); fma2(acc[3][1], a23.y, f.y);
            fma2(acc[4][0], a45.x, f.x); fma2(acc[4][1], a45.x, f.y);
            fma2(acc[5][0], a45.y, f.x); fma2(acc[5][1], a45.y, f.y);
            fma2(acc[6][0], a67.x, f.x); fma2(acc[6][1], a67.x, f.y);
            fma2(acc[7][0], a67.y, f.x); fma2(acc[7][1], a67.y, f.y);
            fma2(acc[8][0], a89.x, f.x); fma2(acc[8][1], a89.x, f.y);
            fma2(acc[9][0], a89.y, f.x); fma2(acc[9][1], a89.y, f.y);
        }
        __syncthreads();               // everyone done with this slot
        if (tid == 0 && st + 2 < NSTG) {
            const int ns = st + 2, nslot = ns % NSLOT;
            mbar_expect_tx(mbA + nslot * 8, RSZ);
            bulk_g2s(ringA + nslot * RSZ, g0 + (ull)ns * RSZ, RSZ, mbA + nslot * 8);
        }
    }

    // ---- reduce the two s-parities; sp==0 writes chunk partial ----
    ull* buf = (ull*)dyn;              // ring no longer in use
    if (sp == 1) {
        ull* rowp = buf + dg * 20;
        #pragma unroll
        for (int k = 0; k < Kn; k++) { rowp[2 * k] = acc[k][0]; rowp[2 * k + 1] = acc[k][1]; }
    }
    __syncthreads();
    if (sp == 0) {
        const ull* rowp = buf + dg * 20;
        float4* gp4 = (float4*)g_part;
        #pragma unroll
        for (int k = 0; k < Kn; k++) {
            fma2(acc[k][0], rowp[2 * k],     ONE2);
            fma2(acc[k][1], rowp[2 * k + 1], ONE2);
            float4 v;
            v.x = __uint_as_float((unsigned int)acc[k][0]);
            v.y = __uint_as_float((unsigned int)(acc[k][0] >> 32));
            v.z = __uint_as_float((unsigned int)acc[k][1]);
            v.w = __uint_as_float((unsigned int)(acc[k][1] >> 32));
            gp4[((size_t)(b * NSC + sc) * Kn + k) * 128 + dg] = v;
        }
    }

    // ---- last CTA of this batch merges 16 chunk partials + normalizes ----
    __threadfence();
    __syncthreads();
    if (tid == 0) {
        int old = atomicAdd(&g_cnt[b], 1);
        isLast = (old == NSC - 1);
    }
    __syncthreads();
    if (!isLast) return;
    __threadfence();

    if (tid < Kn) {
        float s = 0.f;
        #pragma unroll
        for (int c = 0; c < NSC; c++) s += g_asum[b * NSC + c][tid];
        asumT[tid] = s;
    }
    __syncthreads();

    float* sqarr = (float*)dyn;        // 1280 floats
    const float4* gp4 = (const float4*)g_part;
    const float4* cl4 = (const float4*)cluster;
    float4* o4 = (float4*)out + (size_t)b * 1280;

    #pragma unroll
    for (int j = 0; j < 5; j++) {
        const int idx = tid + j * NT;          // 0..1279
        const int k = idx >> 7, c = idx & 127;
        float4 r = make_float4(0.f, 0.f, 0.f, 0.f);
        #pragma unroll
        for (int ch = 0; ch < NSC; ch++) {     // fixed order -> deterministic
            float4 p = gp4[((size_t)(b * NSC + ch) * Kn + k) * 128 + c];
            r.x += p.x; r.y += p.y; r.z += p.z; r.w += p.w;
        }
        const float as = asumT[k];
        float4 cv = cl4[k * 128 + c];
        r.x -= as * cv.x; r.y -= as * cv.y; r.z -= as * cv.z; r.w -= as * cv.w;
        o4[idx] = r;
        sqarr[idx] = r.x * r.x + r.y * r.y + r.z * r.z + r.w * r.w;
    }
    __syncthreads();
    if (tid < Kn) {
        float s = 0.f;
        #pragma unroll
        for (int c = 0; c < 128; c++) s += sqarr[tid * 128 + c];
        invS[tid] = rsqrtf(fmaxf(s, 1e-12f));
    }
    __syncthreads();
    #pragma unroll
    for (int j = 0; j < 5; j++) {
        const int idx = tid + j * NT;
        const float iv = invS[idx >> 7];
        float4 v = o4[idx];
        v.x *= iv; v.y *= iv; v.z *= iv; v.w *= iv;
        o4[idx] = v;
    }
    if (tid == 0) g_cnt[b] = 0;        // reset for next graph replay
}

extern "C" void kernel_launch(void* const* d_in, const int* in_sizes, int n_in,
                              void* d_out, int out_size) {
    const float* feat    = (const float*)d_in[0];  // (16,16,64,512) f32
    const float* score   = (const float*)d_in[1];  // (16,16,64,12)  f32
    const float* cluster = (const float*)d_in[2];  // (12,512)       f32
    float* out = (float*)d_out;                    // (16,5120)      f32

    static int attr_set = 0;
    if (!attr_set) {
        cudaFuncSetAttribute(vlad_bulk, cudaFuncAttributeMaxDynamicSharedMemorySize,
                             DYN_BYTES);
        attr_set = 1;
    }
    vlad_bulk<<<Bn * NSC, NT, DYN_BYTES>>>(feat, score, cluster, out);
}